// round 1
// baseline (speedup 1.0000x reference)
#include <cuda_runtime.h>
#include <cuda_bf16.h>

#define N_NODES_C 100000
#define D_C 64

// Scratch for Y = X @ W  (static __device__ array: allowed, no allocation)
__device__ float g_Y[(size_t)N_NODES_C * D_C];

// ---------------------------------------------------------------------------
// K1: dense GEMM  Y[M,64] = X[M,64] @ W[64,64]
// Block computes a 64(M) x 64(N) tile, 256 threads, 4x4 register tile each.
// K = 64 fits entirely in one shared-memory staging (no k-loop over tiles).
// ---------------------------------------------------------------------------
__global__ __launch_bounds__(256, 4)
void gemm_xw_kernel(const float* __restrict__ X,
                    const float* __restrict__ W,
                    float* __restrict__ Y,
                    int M)
{
    __shared__ float xs[64][65];   // +1 pad: kills 2-way conflict on a-reads
    __shared__ float ws[64][64];

    const int t  = threadIdx.x;
    const int m0 = blockIdx.x * 64;

    // Load W (64x64 floats = 1024 float4) -- 4 float4 per thread
    #pragma unroll
    for (int i = 0; i < 4; i++) {
        int idx = t + i * 256;           // float4 index 0..1023
        int r = idx >> 4;                // row (k)
        int c = (idx & 15) << 2;         // col (n)
        float4 v = ((const float4*)W)[idx];
        ws[r][c + 0] = v.x; ws[r][c + 1] = v.y;
        ws[r][c + 2] = v.z; ws[r][c + 3] = v.w;
    }

    // Load X tile (rows m0..m0+63, all K)
    #pragma unroll
    for (int i = 0; i < 4; i++) {
        int idx = t + i * 256;
        int r = idx >> 4;                // local row
        int c = (idx & 15) << 2;         // k
        float4 v = make_float4(0.f, 0.f, 0.f, 0.f);
        if (m0 + r < M)
            v = ((const float4*)X)[(size_t)(m0 + r) * 16 + (idx & 15)];
        xs[r][c + 0] = v.x; xs[r][c + 1] = v.y;
        xs[r][c + 2] = v.z; xs[r][c + 3] = v.w;
    }
    __syncthreads();

    const int tx = t & 15;    // n-group (4 cols)
    const int ty = t >> 4;    // m-group (4 rows)

    float acc[4][4];
    #pragma unroll
    for (int i = 0; i < 4; i++)
        #pragma unroll
        for (int j = 0; j < 4; j++)
            acc[i][j] = 0.f;

    #pragma unroll
    for (int k = 0; k < 64; k++) {
        float a0 = xs[ty * 4 + 0][k];
        float a1 = xs[ty * 4 + 1][k];
        float a2 = xs[ty * 4 + 2][k];
        float a3 = xs[ty * 4 + 3][k];
        float4 b = *(const float4*)&ws[k][tx * 4];

        acc[0][0] += a0 * b.x; acc[0][1] += a0 * b.y; acc[0][2] += a0 * b.z; acc[0][3] += a0 * b.w;
        acc[1][0] += a1 * b.x; acc[1][1] += a1 * b.y; acc[1][2] += a1 * b.z; acc[1][3] += a1 * b.w;
        acc[2][0] += a2 * b.x; acc[2][1] += a2 * b.y; acc[2][2] += a2 * b.z; acc[2][3] += a2 * b.w;
        acc[3][0] += a3 * b.x; acc[3][1] += a3 * b.y; acc[3][2] += a3 * b.z; acc[3][3] += a3 * b.w;
    }

    #pragma unroll
    for (int i = 0; i < 4; i++) {
        int r = m0 + ty * 4 + i;
        if (r < M) {
            float4 o = make_float4(acc[i][0], acc[i][1], acc[i][2], acc[i][3]);
            ((float4*)Y)[(size_t)r * 16 + tx] = o;
        }
    }
}

// ---------------------------------------------------------------------------
// K2: unweighted CSR segment-sum over Y:  out[i] = sum_{e in [rp[i],rp[i+1])} Y[ci[e]]
// One warp per row; each lane owns a float2 slice (32 lanes x 8B = 256B row).
// Unrolled x4 for memory-level parallelism on the L2-resident gather.
// ---------------------------------------------------------------------------
__global__ __launch_bounds__(256, 8)
void spmm_agg_kernel(const float* __restrict__ Y,
                     const int* __restrict__ rp,
                     const int* __restrict__ ci,
                     float* __restrict__ out)
{
    const int row  = blockIdx.x * 8 + (threadIdx.x >> 5);
    if (row >= N_NODES_C) return;
    const int lane = threadIdx.x & 31;

    const int s = __ldg(rp + row);
    const int e = __ldg(rp + row + 1);

    const float2* __restrict__ Y2 = (const float2*)Y;
    float2 acc = make_float2(0.f, 0.f);

    int k = s;
    for (; k + 4 <= e; k += 4) {
        int c0 = __ldg(ci + k + 0);
        int c1 = __ldg(ci + k + 1);
        int c2 = __ldg(ci + k + 2);
        int c3 = __ldg(ci + k + 3);
        float2 v0 = Y2[(size_t)c0 * 32 + lane];
        float2 v1 = Y2[(size_t)c1 * 32 + lane];
        float2 v2 = Y2[(size_t)c2 * 32 + lane];
        float2 v3 = Y2[(size_t)c3 * 32 + lane];
        acc.x += v0.x; acc.y += v0.y;
        acc.x += v1.x; acc.y += v1.y;
        acc.x += v2.x; acc.y += v2.y;
        acc.x += v3.x; acc.y += v3.y;
    }
    for (; k < e; ++k) {
        int c = __ldg(ci + k);
        float2 v = Y2[(size_t)c * 32 + lane];
        acc.x += v.x; acc.y += v.y;
    }

    ((float2*)out)[(size_t)row * 32 + lane] = acc;
}

// ---------------------------------------------------------------------------
// kernel_launch
// Input order (metadata): 0=X [100000,64] f32, 1=weights [64,64] f32,
// 2=row_pointers [100001] i32, 3=column_index [1600000] i32, 4..6 unused.
// ---------------------------------------------------------------------------
extern "C" void kernel_launch(void* const* d_in, const int* in_sizes, int n_in,
                              void* d_out, int out_size)
{
    const float* X  = (const float*)d_in[0];
    const float* W  = (const float*)d_in[1];
    const int*   rp = (const int*)d_in[2];
    const int*   ci = (const int*)d_in[3];
    float*       out = (float*)d_out;

    const int M = in_sizes[0] / D_C;   // 100000

    float* Y;
    cudaGetSymbolAddress((void**)&Y, g_Y);

    // K1: Y = X @ W
    {
        dim3 grid((M + 63) / 64);
        gemm_xw_kernel<<<grid, 256>>>(X, W, Y, M);
    }

    // K2: out[i] = segment_sum(Y[ci])
    {
        dim3 grid((M + 7) / 8);
        spmm_agg_kernel<<<grid, 256>>>(Y, rp, ci, out);
    }
}

// round 2
// speedup vs baseline: 1.2030x; 1.2030x over previous
#include <cuda_runtime.h>
#include <cuda_fp16.h>

#define N_NODES_C 100000
#define D_C 64

typedef unsigned long long ull;

// Y = X @ W stored as fp16 (halves gather traffic in K2). Static device scratch.
__device__ __half g_Yh[(size_t)N_NODES_C * D_C];

// ---------------------------------------------------------------------------
// Packed f32x2 helpers (Blackwell FFMA2 — only reachable via PTX)
// ---------------------------------------------------------------------------
__device__ __forceinline__ ull pack2(float x, float y) {
    ull r; asm("mov.b64 %0, {%1, %2};" : "=l"(r) : "f"(x), "f"(y)); return r;
}
__device__ __forceinline__ void unpack2(ull v, float& x, float& y) {
    asm("mov.b64 {%0, %1}, %2;" : "=f"(x), "=f"(y) : "l"(v));
}
__device__ __forceinline__ ull ffma2(ull a, ull b, ull c) {
    ull d; asm("fma.rn.f32x2 %0, %1, %2, %3;" : "=l"(d) : "l"(a), "l"(b), "l"(c));
    return d;
}

// ---------------------------------------------------------------------------
// K1: Y[M,64] = X[M,64] @ W[64,64], fp32 math via packed FFMA2, fp16 output.
// Block tile 128(M) x 64(N), 256 threads, thread tile 8m x 4n as 4 m-pairs.
// Shared: X tile transposed [k][m] (pairs along m contiguous -> LDS.64 a-pairs),
//         W duplicated pairs ws2[k][n] = {w,w} in a swizzled layout so the 16
//         tx-lanes hit 128B contiguous per b-load (conflict-free).
// ---------------------------------------------------------------------------
#define TM 128
#define XS_STRIDE 130   // floats; even (8B align for ull loads), 4-way store conflict only
#define XS_FLOATS (64 * XS_STRIDE)
#define SMEM_K1 (XS_FLOATS * 4 + 64 * 64 * 8)

__global__ __launch_bounds__(256)
void gemm_xw_f16out(const float* __restrict__ X,
                    const float* __restrict__ W,
                    __half* __restrict__ Y,
                    int M)
{
    extern __shared__ char smem_raw[];
    float* xs  = (float*)smem_raw;                     // [64][XS_STRIDE]
    ull*   ws2 = (ull*)(smem_raw + XS_FLOATS * 4);     // [64][64] swizzled, {w,w} pairs

    const int t  = threadIdx.x;
    const int m0 = blockIdx.x * TM;

    // W -> duplicated pairs, swizzled: ws2[k*64 + (n&3)*16 + (n>>2)] = {w,w}
    #pragma unroll
    for (int i = 0; i < 16; i++) {
        int idx = t + i * 256;           // 0..4095 == k*64+n
        int k = idx >> 6, n = idx & 63;
        float w = W[idx];
        ws2[k * 64 + (n & 3) * 16 + (n >> 2)] = pack2(w, w);
    }

    // X tile -> transposed xs[k][m]
    #pragma unroll
    for (int i = 0; i < 8; i++) {
        int idx = t + i * 256;           // float4 index 0..2047
        int m  = idx >> 4;               // 0..127
        int k4 = idx & 15;
        float4 v = make_float4(0.f, 0.f, 0.f, 0.f);
        if (m0 + m < M)
            v = ((const float4*)X)[(size_t)(m0 + m) * 16 + k4];
        xs[(k4 * 4 + 0) * XS_STRIDE + m] = v.x;
        xs[(k4 * 4 + 1) * XS_STRIDE + m] = v.y;
        xs[(k4 * 4 + 2) * XS_STRIDE + m] = v.z;
        xs[(k4 * 4 + 3) * XS_STRIDE + m] = v.w;
    }
    __syncthreads();

    const int tx = t & 15;     // n-group: cols tx*4 .. tx*4+3
    const int ty = t >> 4;     // m-group: rows mb .. mb+7
    const int mb = ty * 8;

    ull acc[4][4];             // [m-pair][n] ; pair = (row, row+1)
    #pragma unroll
    for (int i = 0; i < 4; i++)
        #pragma unroll
        for (int j = 0; j < 4; j++)
            acc[i][j] = 0ull;  // bits of (0.f, 0.f)

    const float* xr = xs + mb;
    const ull*   wr = ws2 + tx;    // + k*64 + j*16

    #pragma unroll 8
    for (int k = 0; k < 64; k++) {
        const ull* ap = (const ull*)(xr + k * XS_STRIDE);
        ull a01 = ap[0], a23 = ap[1], a45 = ap[2], a67 = ap[3];
        const ull* bp = wr + k * 64;
        ull b0 = bp[0], b1 = bp[16], b2 = bp[32], b3 = bp[48];

        acc[0][0] = ffma2(a01, b0, acc[0][0]);
        acc[0][1] = ffma2(a01, b1, acc[0][1]);
        acc[0][2] = ffma2(a01, b2, acc[0][2]);
        acc[0][3] = ffma2(a01, b3, acc[0][3]);
        acc[1][0] = ffma2(a23, b0, acc[1][0]);
        acc[1][1] = ffma2(a23, b1, acc[1][1]);
        acc[1][2] = ffma2(a23, b2, acc[1][2]);
        acc[1][3] = ffma2(a23, b3, acc[1][3]);
        acc[2][0] = ffma2(a45, b0, acc[2][0]);
        acc[2][1] = ffma2(a45, b1, acc[2][1]);
        acc[2][2] = ffma2(a45, b2, acc[2][2]);
        acc[2][3] = ffma2(a45, b3, acc[2][3]);
        acc[3][0] = ffma2(a67, b0, acc[3][0]);
        acc[3][1] = ffma2(a67, b1, acc[3][1]);
        acc[3][2] = ffma2(a67, b2, acc[3][2]);
        acc[3][3] = ffma2(a67, b3, acc[3][3]);
    }

    // Store: each m-pair -> two fp16 rows of 4 cols (8B each)
    #pragma unroll
    for (int mp = 0; mp < 4; mp++) {
        int r = m0 + mb + mp * 2;
        float l0, h0, l1, h1, l2, h2, l3, h3;
        unpack2(acc[mp][0], l0, h0);
        unpack2(acc[mp][1], l1, h1);
        unpack2(acc[mp][2], l2, h2);
        unpack2(acc[mp][3], l3, h3);
        if (r < M) {
            __half2 p01 = __floats2half2_rn(l0, l1);
            __half2 p23 = __floats2half2_rn(l2, l3);
            uint2 u = make_uint2(*(unsigned*)&p01, *(unsigned*)&p23);
            *(uint2*)(Y + (size_t)r * 64 + tx * 4) = u;
        }
        if (r + 1 < M) {
            __half2 p01 = __floats2half2_rn(h0, h1);
            __half2 p23 = __floats2half2_rn(h2, h3);
            uint2 u = make_uint2(*(unsigned*)&p01, *(unsigned*)&p23);
            *(uint2*)(Y + (size_t)(r + 1) * 64 + tx * 4) = u;
        }
    }
}

// ---------------------------------------------------------------------------
// K2: out[i] = sum_{e in [rp[i],rp[i+1])} Yh[ci[e]]   (fp32 accumulation)
// One warp per row. 4 lane-groups of 8; each group handles one edge per step,
// each lane loads uint4 = 8 halves (group covers full 128B fp16 row).
// Warp fetches 4 edges per load instruction; unrolled x2 -> MLP 2/lane.
// ---------------------------------------------------------------------------
__global__ __launch_bounds__(256)
void spmm_agg_h(const __half* __restrict__ Y,
                const int* __restrict__ rp,
                const int* __restrict__ ci,
                float* __restrict__ out)
{
    const int row = blockIdx.x * 8 + (threadIdx.x >> 5);
    if (row >= N_NODES_C) return;
    const int lane = threadIdx.x & 31;
    const int g   = lane >> 3;   // edge group 0..3
    const int sub = lane & 7;    // 16B chunk within row

    const int s = __ldg(rp + row);
    const int e = __ldg(rp + row + 1);

    const uint4* __restrict__ base = (const uint4*)Y;  // row c -> base + c*8

    float acc[8];
    #pragma unroll
    for (int j = 0; j < 8; j++) acc[j] = 0.f;

    int k = s;
    for (; k + 8 <= e; k += 8) {
        int c0 = __ldg(ci + k + g);
        int c1 = __ldg(ci + k + 4 + g);
        uint4 v0 = __ldg(base + (size_t)c0 * 8 + sub);
        uint4 v1 = __ldg(base + (size_t)c1 * 8 + sub);
        const __half2* h0 = (const __half2*)&v0;
        const __half2* h1 = (const __half2*)&v1;
        #pragma unroll
        for (int i = 0; i < 4; i++) {
            float2 f0 = __half22float2(h0[i]);
            float2 f1 = __half22float2(h1[i]);
            acc[2 * i + 0] += f0.x + f1.x;
            acc[2 * i + 1] += f0.y + f1.y;
        }
    }
    for (; k < e; k += 4) {
        int idx = k + g;
        if (idx < e) {
            int c = __ldg(ci + idx);
            uint4 v = __ldg(base + (size_t)c * 8 + sub);
            const __half2* h = (const __half2*)&v;
            #pragma unroll
            for (int i = 0; i < 4; i++) {
                float2 f = __half22float2(h[i]);
                acc[2 * i + 0] += f.x;
                acc[2 * i + 1] += f.y;
            }
        }
    }

    // Reduce the 4 groups (lanes xor 8, 16 hold same column range)
    #pragma unroll
    for (int j = 0; j < 8; j++) {
        acc[j] += __shfl_xor_sync(0xffffffff, acc[j], 8);
        acc[j] += __shfl_xor_sync(0xffffffff, acc[j], 16);
    }

    if (lane < 8) {
        float4 o0 = make_float4(acc[0], acc[1], acc[2], acc[3]);
        float4 o1 = make_float4(acc[4], acc[5], acc[6], acc[7]);
        float* op = out + (size_t)row * 64 + sub * 8;
        *(float4*)(op + 0) = o0;
        *(float4*)(op + 4) = o1;
    }
}

// ---------------------------------------------------------------------------
// kernel_launch
// Inputs: 0=X [100000,64] f32, 1=weights [64,64] f32, 2=row_pointers [100001] i32,
//         3=column_index [1600000] i32, 4..6 unused metadata.
// ---------------------------------------------------------------------------
extern "C" void kernel_launch(void* const* d_in, const int* in_sizes, int n_in,
                              void* d_out, int out_size)
{
    const float* X  = (const float*)d_in[0];
    const float* W  = (const float*)d_in[1];
    const int*   rp = (const int*)d_in[2];
    const int*   ci = (const int*)d_in[3];
    float*       out = (float*)d_out;

    const int M = in_sizes[0] / D_C;   // 100000

    __half* Y;
    cudaGetSymbolAddress((void**)&Y, g_Yh);

    // K1: Y = X @ W (fp16 out)
    cudaFuncSetAttribute(gemm_xw_f16out, cudaFuncAttributeMaxDynamicSharedMemorySize, SMEM_K1);
    {
        dim3 grid((M + TM - 1) / TM);
        gemm_xw_f16out<<<grid, 256, SMEM_K1>>>(X, W, Y, M);
    }

    // K2: out = segment_sum(Y[ci])
    {
        dim3 grid((M + 7) / 8);
        spmm_agg_h<<<grid, 256>>>(Y, rp, ci, out);
    }
}